// round 17
// baseline (speedup 1.0000x reference)
#include <cuda_runtime.h>
#include <cuda_fp16.h>
#include <cstdint>

// ---------------- problem constants ----------------
#define BATCH 2
#define NPOS  8000          // 20*20*20
#define NKT   32            // kv tiles of 256 keys: 31 full + 1 tail (64 keys)
#define NITEMS 500          // warp-items per batch (8000 rows / 16)
#define NCPB   72           // CTAs per batch in flash

// -------- device scratch (padded: tail fills read K rows/V keys to 8191) ----
__device__ __half g_Qh[BATCH * NPOS * 64];           // (b, n, k) pre-scaled
__device__ __half g_Kh[BATCH * NPOS * 64 + 16384];   // (b, n, k)
__device__ __half g_Vt[BATCH * 64 * NPOS + 16384];   // (b, c, n) transposed
__device__ __half g_Oh[BATCH * NPOS * 64];           // (b, n, c) f16
__device__ uint32_t g_W16[192 * 36];                 // f16 qkv W image
__device__ float    g_B[192];                        // scaled qkv biases
__device__ uint32_t g_WO16[64 * 36];                 // f16 wo image
__device__ float    g_BO[64];                        // bo

#define QSCALE (0.125f * 1.44269504f)   // 1/sqrt(64) * log2(e), folded into Wq

// ---------------- PTX helpers ----------------
__device__ __forceinline__ uint32_t smem_u32(const void* p) {
    uint32_t a;
    asm("{ .reg .u64 t; cvta.to.shared.u64 t, %1; cvt.u32.u64 %0, t; }"
        : "=r"(a) : "l"(p));
    return a;
}

__device__ __forceinline__ void mma_f16(float d[4], const uint32_t a[4],
                                        const uint32_t b0, const uint32_t b1,
                                        const float c[4]) {
    asm volatile(
        "mma.sync.aligned.m16n8k16.row.col.f32.f16.f16.f32 "
        "{%0,%1,%2,%3}, {%4,%5,%6,%7}, {%8,%9}, {%10,%11,%12,%13};"
        : "=f"(d[0]), "=f"(d[1]), "=f"(d[2]), "=f"(d[3])
        : "r"(a[0]), "r"(a[1]), "r"(a[2]), "r"(a[3]),
          "r"(b0), "r"(b1),
          "f"(c[0]), "f"(c[1]), "f"(c[2]), "f"(c[3]));
}

__device__ __forceinline__ void mma_f16h(uint32_t d[2], const uint32_t a[4],
                                         const uint32_t b0, const uint32_t b1,
                                         const uint32_t c0, const uint32_t c1) {
    asm volatile(
        "mma.sync.aligned.m16n8k16.row.col.f16.f16.f16.f16 "
        "{%0,%1}, {%2,%3,%4,%5}, {%6,%7}, {%8,%9};"
        : "=r"(d[0]), "=r"(d[1])
        : "r"(a[0]), "r"(a[1]), "r"(a[2]), "r"(a[3]),
          "r"(b0), "r"(b1), "r"(c0), "r"(c1));
}

__device__ __forceinline__ void ldsm4(uint32_t& d0, uint32_t& d1,
                                      uint32_t& d2, uint32_t& d3, uint32_t addr) {
    asm volatile("ldmatrix.sync.aligned.m8n8.x4.shared.b16 {%0,%1,%2,%3}, [%4];"
                 : "=r"(d0), "=r"(d1), "=r"(d2), "=r"(d3) : "r"(addr));
}

__device__ __forceinline__ uint32_t ex2h2(uint32_t h) {
    uint32_t r;
    asm("ex2.approx.f16x2 %0, %1;" : "=r"(r) : "r"(h));
    return r;
}

__device__ __forceinline__ void cpasync16(uint32_t dst, const void* src) {
    asm volatile("cp.async.cg.shared.global [%0], [%1], 16;" :: "r"(dst), "l"(src));
}
#define CP_COMMIT() asm volatile("cp.async.commit_group;" ::: "memory")

// ============================================================================
// Kernel 0: weight prep — qkv W image (scales folded) AND wo image + biases.
// ============================================================================
__global__ __launch_bounds__(512) void prep_kernel(
    const float* __restrict__ wq, const float* __restrict__ bq,
    const float* __restrict__ wk, const float* __restrict__ bk,
    const float* __restrict__ wv, const float* __restrict__ bv,
    const float* __restrict__ wo, const float* __restrict__ bo)
{
    const int i = blockIdx.x * 512 + threadIdx.x;
    if (i < 6144) {
        int row = i >> 5, c2 = i & 31;
        const float* wsrc = (row < 64) ? wq : (row < 128) ? wk : wv;
        int r = row & 63;
        float w0 = wsrc[r * 64 + 2 * c2], w1 = wsrc[r * 64 + 2 * c2 + 1];
        if (row < 64) { w0 *= QSCALE; w1 *= QSCALE; }
        __half2 h = __floats2half2_rn(w0, w1);
        g_W16[row * 36 + c2] = *(uint32_t*)&h;
    }
    if (i < 2048) {
        int row = i >> 5, c2 = i & 31;
        __half2 h = __floats2half2_rn(wo[row * 64 + 2 * c2],
                                      wo[row * 64 + 2 * c2 + 1]);
        g_WO16[row * 36 + c2] = *(uint32_t*)&h;
    }
    if (i < 192) {
        g_B[i] = (i < 64) ? bq[i] * QSCALE
               : (i < 128) ? bk[i - 64] : bv[i - 128];
    }
    if (i < 64) g_BO[i] = bo[i];
}

// ============================================================================
// Kernel A: fused QKV projection via mma.sync f16 (round-15/16 verbatim).
// ============================================================================
#define WS_OFF  0
#define XS_OFF  6912
#define QST_OFF 9216
#define KST_OFF 11520
#define VST_OFF 13824
#define BS_OFF  16128
#define QKV_SMEM_BYTES ((16128 + 192) * 4)   // 65,280 B

__global__ __launch_bounds__(128, 3) void qkv_kernel(const float* __restrict__ x)
{
    extern __shared__ uint32_t smw[];
    uint32_t* xs  = smw + XS_OFF;               // [64][36]
    __half*  qst  = (__half*)(smw + QST_OFF);   // [64][72]
    __half*  kst  = (__half*)(smw + KST_OFF);   // [64][72]
    __half*  vst  = (__half*)(smw + VST_OFF);   // [64 chan][72 pos]
    float*   bs   = (float*)(smw + BS_OFF);     // [192]
    const uint32_t sbase = smem_u32(smw);

    const int tid  = threadIdx.x;
    const int wid  = tid >> 5, lane = tid & 31;
    const int g    = lane >> 2, tig = lane & 3;
    const int b    = blockIdx.y;
    const int n0   = blockIdx.x * 64;
    const int p0   = wid * 16;

    for (int i = tid; i < 1728; i += 128)
        cpasync16(sbase + (uint32_t)(i * 16), (const uint4*)g_W16 + i);
    if (tid < 48)
        cpasync16(sbase + (uint32_t)(BS_OFF * 4 + tid * 16), (const uint4*)g_B + tid);
    CP_COMMIT();

    for (int i = tid; i < 2048; i += 128) {
        int c2 = i >> 6, p = i & 63;
        float x0 = x[(b * 64 + 2 * c2    ) * NPOS + n0 + p];
        float x1 = x[(b * 64 + 2 * c2 + 1) * NPOS + n0 + p];
        __half2 h = __floats2half2_rn(x0, x1);
        xs[p * 36 + c2] = *(uint32_t*)&h;
    }
    asm volatile("cp.async.wait_group 0;" ::: "memory");
    __syncthreads();

    const int row_in = (lane & 7) | ((lane >> 4) << 3);
    const int woff   = ((lane >> 3) & 1) << 2;
    const uint32_t xLane = sbase + (uint32_t)((XS_OFF + (p0 + row_in) * 36 + woff) * 4);
    uint32_t bfr[4][4];
#pragma unroll
    for (int kk = 0; kk < 4; ++kk)
        ldsm4(bfr[kk][0], bfr[kk][1], bfr[kk][2], bfr[kk][3],
              xLane + (uint32_t)(kk * 32));

    const uint32_t aLaneBase = sbase
        + (uint32_t)(((lane & 15) * 36) * 4) + (uint32_t)(((lane >> 4) << 4));

    const int pA = p0 + 2 * tig;
    const int pB = pA + 8;

#pragma unroll
    for (int mb = 0; mb < 12; ++mb) {
        float d0[4] = {0.f, 0.f, 0.f, 0.f};
        float d1[4] = {0.f, 0.f, 0.f, 0.f};
        const uint32_t aL = aLaneBase + (uint32_t)(mb * 16 * 36 * 4);
#pragma unroll
        for (int kk = 0; kk < 4; ++kk) {
            uint32_t a[4];
            ldsm4(a[0], a[1], a[2], a[3], aL + (uint32_t)(kk * 32));
            mma_f16(d0, a, bfr[kk][0], bfr[kk][1], d0);
            mma_f16(d1, a, bfr[kk][2], bfr[kk][3], d1);
        }
        const int ch0 = mb * 16 + g, ch1 = ch0 + 8;
        const float bb0 = bs[ch0], bb1 = bs[ch1];
        if (mb < 8) {
            __half* st = (mb < 4) ? qst : kst;
            const int cc0 = ch0 & 63, cc1 = ch1 & 63;
            st[ pA      * 72 + cc0] = __float2half_rn(d0[0] + bb0);
            st[(pA + 1) * 72 + cc0] = __float2half_rn(d0[1] + bb0);
            st[ pA      * 72 + cc1] = __float2half_rn(d0[2] + bb1);
            st[(pA + 1) * 72 + cc1] = __float2half_rn(d0[3] + bb1);
            st[ pB      * 72 + cc0] = __float2half_rn(d1[0] + bb0);
            st[(pB + 1) * 72 + cc0] = __float2half_rn(d1[1] + bb0);
            st[ pB      * 72 + cc1] = __float2half_rn(d1[2] + bb1);
            st[(pB + 1) * 72 + cc1] = __float2half_rn(d1[3] + bb1);
        } else {
            const int cc0 = ch0 - 128, cc1 = ch1 - 128;
            *(__half2*)&vst[cc0 * 72 + pA] = __floats2half2_rn(d0[0] + bb0, d0[1] + bb0);
            *(__half2*)&vst[cc1 * 72 + pA] = __floats2half2_rn(d0[2] + bb1, d0[3] + bb1);
            *(__half2*)&vst[cc0 * 72 + pB] = __floats2half2_rn(d1[0] + bb0, d1[1] + bb0);
            *(__half2*)&vst[cc1 * 72 + pB] = __floats2half2_rn(d1[2] + bb1, d1[3] + bb1);
        }
    }
    __syncthreads();

    for (int i = tid; i < 512; i += 128) {
        int r = i >> 3, c8 = (i & 7) << 3;
        *(uint4*)&g_Qh[((b * NPOS) + n0 + r) * 64 + c8] =
            *(const uint4*)&qst[r * 72 + c8];
        *(uint4*)&g_Kh[((b * NPOS) + n0 + r) * 64 + c8] =
            *(const uint4*)&kst[r * 72 + c8];
    }
    for (int i = tid; i < 512; i += 128) {
        int r = i >> 3, p8 = (i & 7) << 3;
        *(uint4*)&g_Vt[((b * 64) + r) * NPOS + n0 + p8] =
            *(const uint4*)&vst[r * 72 + p8];
    }
}

// ============================================================================
// Kernel B: flash attention (round-14 structure; epilogue now stores f16 O —
// zero added error: outproj already quantized O to f16 in its gather).
// ============================================================================
#define QSTW 36
#define VSTW 132
#define KTILE_B (256 * QSTW * 4)
#define VTILE_B (64 * VSTW * 4)
#define FLASH_SMEM_BYTES (128 * QSTW * 4 + 2 * KTILE_B + 2 * VTILE_B) // 159,744

template<int JMAX>
__device__ __forceinline__ void do_tile(uint32_t kb, uint32_t vb,
                                        const uint32_t qa[4][4],
                                        float ofrag[8][4],
                                        float& lsum0, float& lsum1)
{
    uint32_t sfh[2 * JMAX][2];
#pragma unroll
    for (int nb = 0; nb < 2 * JMAX; ++nb) { sfh[nb][0] = 0u; sfh[nb][1] = 0u; }
#pragma unroll
    for (int k = 0; k < 4; ++k) {
#pragma unroll
        for (int j = 0; j < JMAX; ++j) {
            uint32_t d0, d1, d2, d3;
            ldsm4(d0, d1, d2, d3, kb + (uint32_t)((j * 16 * QSTW + 8 * k) * 4));
            mma_f16h(sfh[2 * j    ], qa[k], d0, d1, sfh[2 * j    ][0], sfh[2 * j    ][1]);
            mma_f16h(sfh[2 * j + 1], qa[k], d2, d3, sfh[2 * j + 1][0], sfh[2 * j + 1][1]);
        }
    }

    uint32_t pa[JMAX][4];
#pragma unroll
    for (int j = 0; j < JMAX; ++j) {
        pa[j][0] = ex2h2(sfh[2 * j    ][0]);
        pa[j][1] = ex2h2(sfh[2 * j    ][1]);
        pa[j][2] = ex2h2(sfh[2 * j + 1][0]);
        pa[j][3] = ex2h2(sfh[2 * j + 1][1]);
    }

    {
        __half2 h0 = __floats2half2_rn(0.f, 0.f);
        __half2 h1 = h0;
#pragma unroll
        for (int j = 0; j < JMAX; ++j) {
            h0 = __hadd2(h0, *(const __half2*)&pa[j][0]);
            h0 = __hadd2(h0, *(const __half2*)&pa[j][2]);
            h1 = __hadd2(h1, *(const __half2*)&pa[j][1]);
            h1 = __hadd2(h1, *(const __half2*)&pa[j][3]);
        }
        lsum0 += __low2float(h0) + __high2float(h0);
        lsum1 += __low2float(h1) + __high2float(h1);
    }

#pragma unroll
    for (int j = 0; j < JMAX; ++j) {
#pragma unroll
        for (int nb2 = 0; nb2 < 4; ++nb2) {
            uint32_t v0, v1, v2, v3;
            ldsm4(v0, v1, v2, v3, vb + (uint32_t)((nb2 * 16 * VSTW + 8 * j) * 4));
            mma_f16(ofrag[2 * nb2    ], pa[j], v0, v1, ofrag[2 * nb2    ]);
            mma_f16(ofrag[2 * nb2 + 1], pa[j], v2, v3, ofrag[2 * nb2 + 1]);
        }
    }
}

__global__ __launch_bounds__(256, 1) void flash_mma_kernel()
{
    extern __shared__ uint32_t smw[];
    uint32_t* Qw = smw;                              // [128][36]
    const uint32_t sbase  = smem_u32(smw);
    const uint32_t kbase0 = sbase + 128 * QSTW * 4;
    const uint32_t vbase0 = kbase0 + 2 * KTILE_B;

    const int tid  = threadIdx.x;
    const int wid  = tid >> 5, lane = tid & 31;
    const int g    = lane >> 2, tig = lane & 3;
    const int b    = blockIdx.x / NCPB;
    const int c    = blockIdx.x % NCPB;
    const int item = c + NCPB * wid;
    const bool valid = (item < NITEMS);
    const int rbase = item * 16;
    const int rb   = wid * 16;

    if (valid) {
#pragma unroll
        for (int i = 0; i < 4; ++i) {
            int idx = lane + 32 * i;
            int rr = idx >> 3, c8 = (idx & 7) << 3;
            uint4 v = *(const uint4*)&g_Qh[((b * NPOS) + rbase + rr) * 64 + c8];
            *(uint4*)&Qw[(rb + rr) * QSTW + (c8 >> 1)] = v;
        }
    }
    __syncthreads();

    uint32_t qa[4][4];
#pragma unroll
    for (int k = 0; k < 4; ++k) {
        qa[k][0] = Qw[(rb + g    ) * QSTW + 8 * k + tig];
        qa[k][1] = Qw[(rb + g + 8) * QSTW + 8 * k + tig];
        qa[k][2] = Qw[(rb + g    ) * QSTW + 8 * k + tig + 4];
        qa[k][3] = Qw[(rb + g + 8) * QSTW + 8 * k + tig + 4];
    }

    const int row_in = (lane & 7) | ((lane >> 4) << 3);
    const int woff   = ((lane >> 3) & 1) << 2;
    const uint32_t kLane = (uint32_t)((row_in * QSTW + woff) * 4);
    const uint32_t vLane = (uint32_t)((row_in * VSTW + woff) * 4);

    float ofrag[8][4];
#pragma unroll
    for (int nb = 0; nb < 8; ++nb)
#pragma unroll
        for (int i = 0; i < 4; ++i) ofrag[nb][i] = 0.f;
    float lsum0 = 0.f, lsum1 = 0.f;

    auto fill_async = [&](int t, uint32_t kdst, uint32_t vdst) {
        const int kv0 = t * 256;
#pragma unroll
        for (int i = 0; i < 8; ++i) {
            int idx = tid + i * 256;
            int r = idx >> 3, c8 = (idx & 7) << 3;
            cpasync16(kdst + (uint32_t)((r * QSTW + (c8 >> 1)) * 4),
                      &g_Kh[((size_t)(b * NPOS) + kv0 + r) * 64 + c8]);
        }
#pragma unroll
        for (int i = 0; i < 8; ++i) {
            int idx = tid + i * 256;
            int cc = idx >> 5, k8 = (idx & 31) << 3;
            cpasync16(vdst + (uint32_t)((cc * VSTW + (k8 >> 1)) * 4),
                      &g_Vt[((size_t)(b * 64) + cc) * NPOS + kv0 + k8]);
        }
    };

    fill_async(0, kbase0, vbase0);
    CP_COMMIT();

#pragma unroll 1
    for (int t = 0; t < NKT; ++t) {
        __syncthreads();
        const int cur = t & 1;
        if (t + 1 < NKT) {
            fill_async(t + 1, kbase0 + (uint32_t)(((t + 1) & 1) * KTILE_B),
                              vbase0 + (uint32_t)(((t + 1) & 1) * VTILE_B));
            CP_COMMIT();
            asm volatile("cp.async.wait_group 1;" ::: "memory");
        } else {
            asm volatile("cp.async.wait_group 0;" ::: "memory");
        }
        __syncthreads();

        if (!valid) continue;

        const uint32_t kb = kbase0 + (uint32_t)(cur * KTILE_B) + kLane;
        const uint32_t vb = vbase0 + (uint32_t)(cur * VTILE_B) + vLane;

        if (t < NKT - 1) {
            do_tile<8>(kb, vb, qa, ofrag, lsum0, lsum1);
            do_tile<8>(kb + (uint32_t)(128 * QSTW * 4), vb + 256u,
                       qa, ofrag, lsum0, lsum1);
        } else {
            do_tile<4>(kb, vb, qa, ofrag, lsum0, lsum1);
        }
    }

    if (!valid) return;

    lsum0 += __shfl_xor_sync(0xffffffffu, lsum0, 1);
    lsum0 += __shfl_xor_sync(0xffffffffu, lsum0, 2);
    lsum1 += __shfl_xor_sync(0xffffffffu, lsum1, 1);
    lsum1 += __shfl_xor_sync(0xffffffffu, lsum1, 2);
    const float inv0 = 1.0f / lsum0;
    const float inv1 = 1.0f / lsum1;

    const int r0 = rbase + g, r1 = rbase + g + 8;
#pragma unroll
    for (int nb = 0; nb < 8; ++nb) {
        *(__half2*)&g_Oh[((b * NPOS) + r0) * 64 + nb * 8 + 2 * tig]
            = __floats2half2_rn(ofrag[nb][0] * inv0, ofrag[nb][1] * inv0);
        *(__half2*)&g_Oh[((b * NPOS) + r1) * 64 + nb * 8 + 2 * tig]
            = __floats2half2_rn(ofrag[nb][2] * inv1, ofrag[nb][3] * inv1);
    }
}

// ============================================================================
// Kernel C: output projection via mma.sync f16 (round-16 structure; O gather
// now reads f16 directly — half the read traffic, no cvt).
//   y[b,o,p] = bo[o] + sum_c wo[o,c] * O[b, c*125 + (p>>6), p&63]
// ============================================================================
#define OP_WO_OFF 0
#define OP_OS_OFF 2304
#define OP_BO_OFF 4608
#define OP_SMEM_BYTES ((4608 + 64) * 4)   // 18,688 B

__global__ __launch_bounds__(128) void out_proj_kernel(float* __restrict__ out)
{
    extern __shared__ uint32_t smw[];
    __half* osh = (__half*)(smw + OP_OS_OFF);   // [64 pos][72 half]
    float*  bos = (float*)(smw + OP_BO_OFF);    // [64]
    const uint32_t sbase = smem_u32(smw);

    const int tid  = threadIdx.x;
    const int wid  = tid >> 5, lane = tid & 31;
    const int g    = lane >> 2, tig = lane & 3;
    const int b    = blockIdx.y;
    const int bx   = blockIdx.x;      // position tile: p = bx*64 + pl
    const int p0   = wid * 16;        // this warp's 16 positions

    for (int i = tid; i < 576; i += 128)
        cpasync16(sbase + (uint32_t)(i * 16), (const uint4*)g_WO16 + i);
    if (tid < 16)
        cpasync16(sbase + (uint32_t)(OP_BO_OFF * 4 + tid * 16), (const uint4*)g_BO + tid);
    CP_COMMIT();

    // ---- gather O (reinterpret reshape): f16 half-pairs, coalesced ----
    for (int i = tid; i < 2048; i += 128) {
        int c = i >> 5, p2 = (i & 31) << 1;     // channel c, positions p2, p2+1
        uint32_t v = *(const uint32_t*)&g_Oh[((b * NPOS) + c * 125 + bx) * 64 + p2];
        osh[ p2      * 72 + c] = ((const __half*)&v)[0];
        osh[(p2 + 1) * 72 + c] = ((const __half*)&v)[1];
    }
    asm volatile("cp.async.wait_group 0;" ::: "memory");
    __syncthreads();

    const int row_in = (lane & 7) | ((lane >> 4) << 3);
    const int woff   = ((lane >> 3) & 1) << 2;
    const uint32_t xLane = sbase + (uint32_t)((OP_OS_OFF + (p0 + row_in) * 36 + woff) * 4);
    uint32_t bfr[4][4];
#pragma unroll
    for (int kk = 0; kk < 4; ++kk)
        ldsm4(bfr[kk][0], bfr[kk][1], bfr[kk][2], bfr[kk][3],
              xLane + (uint32_t)(kk * 32));

    const uint32_t aLaneBase = sbase
        + (uint32_t)(((lane & 15) * 36) * 4) + (uint32_t)(((lane >> 4) << 4));

    const int pA = p0 + 2 * tig;
    const int pB = pA + 8;

#pragma unroll
    for (int mb = 0; mb < 4; ++mb) {
        float d0[4] = {0.f, 0.f, 0.f, 0.f};
        float d1[4] = {0.f, 0.f, 0.f, 0.f};
        const uint32_t aL = aLaneBase + (uint32_t)(mb * 16 * 36 * 4);
#pragma unroll
        for (int kk = 0; kk < 4; ++kk) {
            uint32_t a[4];
            ldsm4(a[0], a[1], a[2], a[3], aL + (uint32_t)(kk * 32));
            mma_f16(d0, a, bfr[kk][0], bfr[kk][1], d0);
            mma_f16(d1, a, bfr[kk][2], bfr[kk][3], d1);
        }
        const int ch0 = mb * 16 + g, ch1 = ch0 + 8;
        const float bb0 = bos[ch0], bb1 = bos[ch1];
        float* o0 = &out[((b * 64) + ch0) * NPOS + bx * 64];
        float* o1 = &out[((b * 64) + ch1) * NPOS + bx * 64];
        *(float2*)&o0[pA] = make_float2(d0[0] + bb0, d0[1] + bb0);
        *(float2*)&o1[pA] = make_float2(d0[2] + bb1, d0[3] + bb1);
        *(float2*)&o0[pB] = make_float2(d1[0] + bb0, d1[1] + bb0);
        *(float2*)&o1[pB] = make_float2(d1[2] + bb1, d1[3] + bb1);
    }
}

// ============================================================================
extern "C" void kernel_launch(void* const* d_in, const int* in_sizes, int n_in,
                              void* d_out, int out_size)
{
    (void)in_sizes; (void)n_in; (void)out_size;
    const float* x  = (const float*)d_in[0];
    const float* wq = (const float*)d_in[1];
    const float* bq = (const float*)d_in[2];
    const float* wk = (const float*)d_in[3];
    const float* bk = (const float*)d_in[4];
    const float* wv = (const float*)d_in[5];
    const float* bv = (const float*)d_in[6];
    const float* wo = (const float*)d_in[7];
    const float* bo = (const float*)d_in[8];
    float* out = (float*)d_out;

    cudaFuncSetAttribute(qkv_kernel,
                         cudaFuncAttributeMaxDynamicSharedMemorySize, QKV_SMEM_BYTES);
    cudaFuncSetAttribute(flash_mma_kernel,
                         cudaFuncAttributeMaxDynamicSharedMemorySize, FLASH_SMEM_BYTES);
    cudaFuncSetAttribute(out_proj_kernel,
                         cudaFuncAttributeMaxDynamicSharedMemorySize, OP_SMEM_BYTES);

    prep_kernel<<<12, 512>>>(wq, bq, wk, bk, wv, bv, wo, bo);
    qkv_kernel<<<dim3(125, BATCH), 128, QKV_SMEM_BYTES>>>(x);
    flash_mma_kernel<<<BATCH * NCPB, 256, FLASH_SMEM_BYTES>>>();
    out_proj_kernel<<<dim3(125, BATCH), 128, OP_SMEM_BYTES>>>(out);
}